// round 7
// baseline (speedup 1.0000x reference)
#include <cuda_runtime.h>

// ConvolutionalCapsule EM-routing. One CTA (1024 threads) per output position.
// Thread (o, i_lo, ph) owns votes v[r][k] for i = i_lo + 16r (r=0..8) and
// pp = 4*ph + k (k=0..3): 36 vote registers -> ~60 live regs, no spill,
// 32 warps/SM. M-step: 27-shuffle intra-warp reduce + one SMEM warp-pair
// exchange. E-step: register FMA + 2 quad shuffles per r.
//
// tid: o = tid>>6 (warp pair), u = tid&63, i_lo = u>>2, ph = u&3.
// warp w = tid>>5; warps 2o (i_lo 0..7) and 2o+1 (i_lo 8..15).

#define BATCH   8
#define HW      14
#define OHW     12
#define NPOS    (BATCH * OHW * OHW)   // 1152
#define NI      144
#define RSTR    152
#define CAP_EPS 1e-9f

// SMEM floats: pose 2880 | rp 2432 | z 2448 | a 144 | xbuf 32*40=1280
#define OFF_RP   2880
#define OFF_Z    (OFF_RP + 16*RSTR)
#define OFF_A    (OFF_Z + NI*17)
#define OFF_X    (OFF_A + NI)
#define SMEM_FLOATS (OFF_X + 32*40)     // 9184
#define SMEM_BYTES  (SMEM_FLOATS * 4)   // 36736 B

__global__ __launch_bounds__(1024, 1)
void capsule_em_kernel(const float* __restrict__ g_pose,
                       const float* __restrict__ g_act,
                       const float* __restrict__ g_w,
                       const float* __restrict__ g_bv,
                       const float* __restrict__ g_ba,
                       float* __restrict__ out)
{
    extern __shared__ float sm[];
    float* pose_sh = sm;              // [i*20 + 4*x + y] (float4 stride 5)
    float* rp_sm   = sm + OFF_RP;     // rr' = rr * a, [o*152 + i]
    float* z_sm    = sm + OFF_Z;      // [i*17 + o]
    float* a_sh    = sm + OFF_A;      // [i]
    float* xbuf    = sm + OFF_X;      // [warp*40 + ph*10 + j]

    const int tid  = threadIdx.x;
    const int lane = tid & 31;
    const int warp = tid >> 5;
    const int o    = tid >> 6;
    const int u    = tid & 63;
    const int i_lo = u >> 2;
    const int ph   = u & 3;

    const int n   = blockIdx.x;
    const int b   = n / (OHW * OHW);
    const int rem = n - b * (OHW * OHW);
    const int h0  = rem / OHW;
    const int w0  = rem - h0 * OHW;

    // ---- Stage pose tile + activations + rr' init ----
    {
        const float4* gp4 = (const float4*)g_pose;
        float4* ps4 = (float4*)pose_sh;
        if (tid < 576) {
            int kk = tid >> 6;            // patch 0..8
            int c4 = tid & 63;            // cap*4 + x
            int di = kk / 3, dj = kk - di * 3;
            int pix = (b * HW + h0 + di) * HW + (w0 + dj);
            int cap = c4 >> 2, x = c4 & 3;
            ps4[(kk * 16 + cap) * 5 + x] = gp4[pix * 64 + c4];
        }
        if (tid < NI) {
            int kk = tid >> 4;
            int cap = tid & 15;
            int di = kk / 3, dj = kk - di * 3;
            int pix = (b * HW + h0 + di) * HW + (w0 + dj);
            a_sh[tid] = g_act[pix * 16 + cap];
        }
    }
    __syncthreads();

    for (int idx = tid; idx < 16 * NI; idx += 1024) {
        int oo = idx / NI;
        int ii = idx - oo * NI;
        rp_sm[oo * RSTR + ii] = a_sh[ii] * 0.0625f;
    }

    // ---- Votes straight into registers ----
    // v[r*4+z] = sum_y pose[i][ph][y] * w[i][o][y][z]  (pose row x = ph)
    float v[36];
    {
        const float4* w4 = (const float4*)g_w;       // [i*64 + o*4 + y]
        const float4* p4 = (const float4*)pose_sh;   // [i*5 + x]
        #pragma unroll
        for (int r = 0; r < 9; r++) {
            int i = i_lo + 16 * r;
            float4 pa  = p4[i * 5 + ph];
            float4 wr0 = w4[i * 64 + o * 4 + 0];
            float4 wr1 = w4[i * 64 + o * 4 + 1];
            float4 wr2 = w4[i * 64 + o * 4 + 2];
            float4 wr3 = w4[i * 64 + o * 4 + 3];
            v[r*4 + 0] = pa.x*wr0.x + pa.y*wr1.x + pa.z*wr2.x + pa.w*wr3.x;
            v[r*4 + 1] = pa.x*wr0.y + pa.y*wr1.y + pa.z*wr2.y + pa.w*wr3.y;
            v[r*4 + 2] = pa.x*wr0.z + pa.y*wr1.z + pa.z*wr2.z + pa.w*wr3.z;
            v[r*4 + 3] = pa.x*wr0.w + pa.y*wr1.w + pa.z*wr2.w + pa.w*wr3.w;
        }
    }
    __syncthreads();

    // ---- EM routing ----
    const float bvo = g_bv[o];
    const float bao = g_ba[o];
    float mean[4], iv[4];
    float act = 0.0f;

    #pragma unroll 1
    for (int t = 0; t < 3; t++) {
        const float inv_temp = 1.0f + (float)t;

        // M-step: per-thread partial moments over my 9 i's
        float S0 = 0.0f, S1[4] = {0,0,0,0}, S2[4] = {0,0,0,0};
        #pragma unroll
        for (int r = 0; r < 9; r++) {
            float q = rp_sm[o * RSTR + i_lo + 16 * r];
            S0 += q;
            #pragma unroll
            for (int k = 0; k < 4; k++) {
                float vv = v[r*4 + k];
                S1[k] = fmaf(q, vv, S1[k]);
                S2[k] = fmaf(q * vv, vv, S2[k]);
            }
        }
        // intra-warp reduce over the 8 in-warp i_lo (lane bits 2..4)
        #pragma unroll
        for (int m = 4; m <= 16; m <<= 1) {
            S0 += __shfl_xor_sync(0xffffffffu, S0, m);
            #pragma unroll
            for (int k = 0; k < 4; k++) {
                S1[k] += __shfl_xor_sync(0xffffffffu, S1[k], m);
                S2[k] += __shfl_xor_sync(0xffffffffu, S2[k], m);
            }
        }
        // cross-warp (partner = warp^1, same o) exchange via SMEM
        if (lane < 4) {
            float* xb = xbuf + warp * 40 + lane * 10;
            xb[0] = S0;
            xb[1] = S1[0]; xb[2] = S1[1]; xb[3] = S1[2]; xb[4] = S1[3];
            xb[5] = S2[0]; xb[6] = S2[1]; xb[7] = S2[2]; xb[8] = S2[3];
        }
        __syncthreads();
        {
            const float* xb = xbuf + (warp ^ 1) * 40 + ph * 10;
            S0 += xb[0];
            S1[0] += xb[1]; S1[1] += xb[2]; S1[2] += xb[3]; S1[3] += xb[4];
            S2[0] += xb[5]; S2[1] += xb[6]; S2[2] += xb[7]; S2[3] += xb[8];
        }

        float invS0 = __fdividef(1.0f, S0);
        float Lh = 0.0f;
        #pragma unroll
        for (int k = 0; k < 4; k++) {
            mean[k] = S1[k] * invS0;
            float var = fmaxf(S2[k] * invS0 - mean[k] * mean[k], 0.0f);
            float stdv = sqrtf(var);
            Lh += __logf(stdv + CAP_EPS);
            iv[k] = __fdividef(1.0f, 2.0f * var + CAP_EPS);
        }
        // L = sum over all 16 pp: reduce over the 4 ph lanes (lane bits 0,1)
        Lh += __shfl_xor_sync(0xffffffffu, Lh, 1);
        Lh += __shfl_xor_sync(0xffffffffu, Lh, 2);
        const float L = Lh;

        float cost = S0 * (16.0f * bvo + L);
        act = 1.0f / (1.0f + __expf(-inv_temp * (bao - cost)));

        if (t < 2) {
            // E-step: register distances + quad reduce
            float zc = __logf(act + CAP_EPS) - L;
            #pragma unroll
            for (int r = 0; r < 9; r++) {
                float d0 = v[r*4+0] - mean[0];
                float d1 = v[r*4+1] - mean[1];
                float d2 = v[r*4+2] - mean[2];
                float d3 = v[r*4+3] - mean[3];
                float s = d0 * iv[0] * d0;
                s = fmaf(d1 * iv[1], d1, s);
                s = fmaf(d2 * iv[2], d2, s);
                s = fmaf(d3 * iv[3], d3, s);
                s += __shfl_xor_sync(0xffffffffu, s, 1);
                s += __shfl_xor_sync(0xffffffffu, s, 2);
                if (ph == 0)
                    z_sm[(i_lo + 16 * r) * 17 + o] = zc - s;
            }
            __syncthreads();

            // softmax over o per input capsule i, spread over 576 threads:
            // thread (i = tid>>2, oq = tid&3) handles oo = oq*4..oq*4+3
            if (tid < 4 * NI) {
                int i  = tid >> 2;
                int oq = tid & 3;
                float z0 = z_sm[i * 17 + oq * 4 + 0];
                float z1 = z_sm[i * 17 + oq * 4 + 1];
                float z2 = z_sm[i * 17 + oq * 4 + 2];
                float z3 = z_sm[i * 17 + oq * 4 + 3];
                float zmax = fmaxf(fmaxf(z0, z1), fmaxf(z2, z3));
                zmax = fmaxf(zmax, __shfl_xor_sync(0xffffffffu, zmax, 1));
                zmax = fmaxf(zmax, __shfl_xor_sync(0xffffffffu, zmax, 2));
                z0 = __expf(z0 - zmax);
                z1 = __expf(z1 - zmax);
                z2 = __expf(z2 - zmax);
                z3 = __expf(z3 - zmax);
                float se = (z0 + z1) + (z2 + z3);
                se += __shfl_xor_sync(0xffffffffu, se, 1);
                se += __shfl_xor_sync(0xffffffffu, se, 2);
                float scale = __fdividef(a_sh[i], se);
                rp_sm[(oq * 4 + 0) * RSTR + i] = z0 * scale;
                rp_sm[(oq * 4 + 1) * RSTR + i] = z1 * scale;
                rp_sm[(oq * 4 + 2) * RSTR + i] = z2 * scale;
                rp_sm[(oq * 4 + 3) * RSTR + i] = z3 * scale;
            }
            __syncthreads();
        }
    }

    // ---- Outputs: pose [N,16,4,4] then activation [N,16] ----
    if (i_lo == 0) {
        #pragma unroll
        for (int k = 0; k < 4; k++)
            out[n * 256 + o * 16 + ph * 4 + k] = mean[k];
        if (ph == 0)
            out[NPOS * 256 + n * 16 + o] = act;
    }
}

extern "C" void kernel_launch(void* const* d_in, const int* in_sizes, int n_in,
                              void* d_out, int out_size)
{
    const float* g_pose = (const float*)d_in[0];
    const float* g_act  = (const float*)d_in[1];
    const float* g_w    = (const float*)d_in[2];
    const float* g_bv   = (const float*)d_in[3];
    const float* g_ba   = (const float*)d_in[4];
    float* out = (float*)d_out;

    cudaFuncSetAttribute(capsule_em_kernel,
                         cudaFuncAttributeMaxDynamicSharedMemorySize, SMEM_BYTES);
    capsule_em_kernel<<<NPOS, 1024, SMEM_BYTES>>>(g_pose, g_act, g_w, g_bv, g_ba, out);
}

// round 8
// speedup vs baseline: 1.1082x; 1.1082x over previous
#include <cuda_runtime.h>

// ConvolutionalCapsule EM-routing, fully fused, one CTA (256 thr) per position.
// Thread (o,p) owns all 144 votes in registers (loaded once from SMEM votes_t).
// M-step: register FMA sweep (+ broadcast rr float4 LDS).
// E-step: NO vote LDS — each lane computes tau_i = (v_i-mean)^2*iv from its
// registers, then a 16-lane reduce-scatter (masks 8,4,2,1) leaves lane p with
// the full p-sum for i == p (mod 16); one STS per 16-i block.

#define BATCH   8
#define HW      14
#define OHW     12
#define NPOS    (BATCH * OHW * OHW)   // 1152
#define NI      144
#define VSTR    148                   // words per (o,p) row in votes_t
#define RSTR    152                   // words per o in rr' (rp)
#define CAP_EPS 1e-9f

#define VROWOFF(o, p) (((o)*16 + (p)) * VSTR + 16 * (o))

// SMEM layout (floats)
#define OFF_POSE 38144                // votes_t occupies [0, 38124)
#define OFF_RP   (OFF_POSE + 144*20)
#define OFF_Z    (OFF_RP + 16*RSTR)
#define OFF_A    (OFF_Z + NI*17)
#define SMEM_FLOATS (OFF_A + NI)
#define SMEM_BYTES  (SMEM_FLOATS * 4) // 184192 B < 227 KB, 1 CTA/SM

__global__ __launch_bounds__(256, 1)
void capsule_em_kernel(const float* __restrict__ g_pose,
                       const float* __restrict__ g_act,
                       const float* __restrict__ g_w,
                       const float* __restrict__ g_bv,
                       const float* __restrict__ g_ba,
                       float* __restrict__ out)
{
    extern __shared__ float sm[];
    float* votes_t = sm;
    float* pose_sh = sm + OFF_POSE;   // [i*20 + 4*x + y] (float4 stride 5)
    float* rp_sm   = sm + OFF_RP;     // rr' = rr * a, layout [o*152 + i]
    float* z_sm    = sm + OFF_Z;      // [i*17 + o]
    float* a_sh    = sm + OFF_A;      // [i]

    const int tid = threadIdx.x;
    const int n   = blockIdx.x;
    const int b   = n / (OHW * OHW);
    const int rem = n - b * (OHW * OHW);
    const int h0  = rem / OHW;
    const int w0  = rem - h0 * OHW;

    const int o = tid >> 4;   // output capsule
    const int p = tid & 15;   // pose elem

    // ---- Stage pose tile + activations ----
    {
        const float4* gp4 = (const float4*)g_pose;
        float4* ps4 = (float4*)pose_sh;
        #pragma unroll
        for (int idx = tid; idx < 576; idx += 256) {
            int kk = idx >> 6;            // patch 0..8
            int c4 = idx & 63;            // cap*4 + x
            int di = kk / 3, dj = kk - di * 3;
            int pix = (b * HW + h0 + di) * HW + (w0 + dj);
            int cap = c4 >> 2, x = c4 & 3;
            ps4[(kk * 16 + cap) * 5 + x] = gp4[pix * 64 + c4];
        }
        if (tid < NI) {
            int kk = tid >> 4;
            int cap = tid & 15;
            int di = kk / 3, dj = kk - di * 3;
            int pix = (b * HW + h0 + di) * HW + (w0 + dj);
            a_sh[tid] = g_act[pix * 16 + cap];
        }
    }
    __syncthreads();

    // ---- Votes + rr' init.  votes[i][o][x][z] = sum_y pose[i][x][y]*w[i][o][y][z]
    {
        const float4* w4 = (const float4*)g_w;       // [i*64 + o*4 + y]
        const float4* p4 = (const float4*)pose_sh;   // [i*5 + x]
        #pragma unroll
        for (int j = 0; j < 9; j++) {
            int i = p + 16 * j;
            float4 pr0 = p4[i * 5 + 0];
            float4 pr1 = p4[i * 5 + 1];
            float4 pr2 = p4[i * 5 + 2];
            float4 pr3 = p4[i * 5 + 3];
            float4 wr0 = w4[i * 64 + o * 4 + 0];
            float4 wr1 = w4[i * 64 + o * 4 + 1];
            float4 wr2 = w4[i * 64 + o * 4 + 2];
            float4 wr3 = w4[i * 64 + o * 4 + 3];
            float* vdst = votes_t + VROWOFF(o, 0) + i;
            #define VROW(PR, X) {                                              \
                vdst[(4*(X)+0)*VSTR] = PR.x*wr0.x + PR.y*wr1.x + PR.z*wr2.x + PR.w*wr3.x; \
                vdst[(4*(X)+1)*VSTR] = PR.x*wr0.y + PR.y*wr1.y + PR.z*wr2.y + PR.w*wr3.y; \
                vdst[(4*(X)+2)*VSTR] = PR.x*wr0.z + PR.y*wr1.z + PR.z*wr2.z + PR.w*wr3.z; \
                vdst[(4*(X)+3)*VSTR] = PR.x*wr0.w + PR.y*wr1.w + PR.z*wr2.w + PR.w*wr3.w; }
            VROW(pr0, 0)
            VROW(pr1, 1)
            VROW(pr2, 2)
            VROW(pr3, 3)
            #undef VROW
            rp_sm[o * RSTR + i] = a_sh[i] * 0.0625f;   // rr(1/16) * a
        }
    }
    __syncthreads();

    // ---- EM routing ----
    const float bvo = g_bv[o];
    const float bao = g_ba[o];
    float mean = 0.0f, act = 0.0f;

    float4 vreg[36];   // this thread's 144 votes, register-resident after t=0
    const float* vsc = (const float*)vreg;

    #define MACC(V, Q) {                                                   \
        A0.x += Q.x;                 A0.y += Q.y;                          \
        A0.z += Q.z;                 A0.w += Q.w;                          \
        A1.x = fmaf(Q.x, V.x, A1.x); A1.y = fmaf(Q.y, V.y, A1.y);          \
        A1.z = fmaf(Q.z, V.z, A1.z); A1.w = fmaf(Q.w, V.w, A1.w);          \
        A2.x = fmaf(Q.x * V.x, V.x, A2.x); A2.y = fmaf(Q.y * V.y, V.y, A2.y); \
        A2.z = fmaf(Q.z * V.z, V.z, A2.z); A2.w = fmaf(Q.w * V.w, V.w, A2.w); }

    #pragma unroll 1
    for (int t = 0; t < 3; t++) {
        const float inv_temp = 1.0f + (float)t;

        // M-step: weighted moments over i for this (o,p)
        float4 A0 = {0,0,0,0}, A1 = {0,0,0,0}, A2 = {0,0,0,0};
        {
            const float4* rr = (const float4*)(rp_sm + o * RSTR);  // broadcast
            if (t == 0) {
                const float4* vr = (const float4*)(votes_t + VROWOFF(o, p));
                #pragma unroll
                for (int r = 0; r < 36; r++) {
                    float4 v = vr[r];
                    vreg[r] = v;                 // stash for t=1,2
                    float4 q = rr[r];
                    MACC(v, q)
                }
            } else {
                #pragma unroll
                for (int r = 0; r < 36; r++) {
                    float4 v = vreg[r];          // register-resident
                    float4 q = rr[r];
                    MACC(v, q)
                }
            }
        }
        float S0 = (A0.x + A0.y) + (A0.z + A0.w);
        float S1 = (A1.x + A1.y) + (A1.z + A1.w);
        float S2 = (A2.x + A2.y) + (A2.z + A2.w);

        float invS0 = __fdividef(1.0f, S0);
        mean = S1 * invS0;
        float var  = fmaxf(S2 * invS0 - mean * mean, 0.0f);
        float stdv = sqrtf(var);
        float lstd = __logf(stdv + CAP_EPS);

        // L = sum_p log(std+eps): 16-lane butterfly
        float L = lstd;
        #pragma unroll
        for (int m = 8; m; m >>= 1) L += __shfl_xor_sync(0xffffffffu, L, m);

        float cost = S0 * (16.0f * bvo + L);
        act = 1.0f / (1.0f + __expf(-inv_temp * (bao - cost)));

        if (t < 2) {
            // E-step, register-only: tau_i = (v_i - mean)^2 * iv for my p,
            // then 16-lane reduce-scatter so lane p gets the p-sum for i==p.
            float iv = __fdividef(1.0f, 2.0f * var + CAP_EPS);
            float zc = __logf(act + CAP_EPS) - L;

            #pragma unroll
            for (int r = 0; r < 9; r++) {
                float tt[16];
                #pragma unroll
                for (int j = 0; j < 16; j++) {
                    float d = vsc[16 * r + j] - mean;
                    tt[j] = d * iv * d;
                }
                #pragma unroll
                for (int m = 8; m >= 1; m >>= 1) {
                    const bool hi = (p & m) != 0;
                    #pragma unroll
                    for (int j = 0; j < 16; j++) {
                        if (j < m) {
                            float send = hi ? tt[j] : tt[j + m];
                            float recv = __shfl_xor_sync(0xffffffffu, send, m);
                            tt[j] = (hi ? tt[j + m] : tt[j]) + recv;
                        }
                    }
                }
                z_sm[(p + 16 * r) * 17 + o] = zc - tt[0];
            }
            __syncthreads();

            // softmax over o per input capsule i; fold a into rr'
            if (tid < NI) {
                float zr[16];
                float zmax = -1e30f;
                #pragma unroll
                for (int oo = 0; oo < 16; oo++) {
                    zr[oo] = z_sm[tid * 17 + oo];
                    zmax = fmaxf(zmax, zr[oo]);
                }
                float se = 0.0f;
                #pragma unroll
                for (int oo = 0; oo < 16; oo++) {
                    zr[oo] = __expf(zr[oo] - zmax);
                    se += zr[oo];
                }
                float scale = __fdividef(a_sh[tid], se);
                #pragma unroll
                for (int oo = 0; oo < 16; oo++)
                    rp_sm[oo * RSTR + tid] = zr[oo] * scale;
            }
            __syncthreads();
        }
    }
    #undef MACC

    // ---- Outputs: pose [N,16,4,4] then activation [N,16] ----
    out[n * 256 + tid] = mean;
    if (p == 0) out[NPOS * 256 + n * 16 + o] = act;
}

extern "C" void kernel_launch(void* const* d_in, const int* in_sizes, int n_in,
                              void* d_out, int out_size)
{
    const float* g_pose = (const float*)d_in[0];
    const float* g_act  = (const float*)d_in[1];
    const float* g_w    = (const float*)d_in[2];
    const float* g_bv   = (const float*)d_in[3];
    const float* g_ba   = (const float*)d_in[4];
    float* out = (float*)d_out;

    cudaFuncSetAttribute(capsule_em_kernel,
                         cudaFuncAttributeMaxDynamicSharedMemorySize, SMEM_BYTES);
    capsule_em_kernel<<<NPOS, 256, SMEM_BYTES>>>(g_pose, g_act, g_w, g_bv, g_ba, out);
}